// round 13
// baseline (speedup 1.0000x reference)
#include <cuda_runtime.h>
#include <cuda_bf16.h>
#include <math.h>
#include <stdint.h>

// ---------------------------------------------------------------------------
// Problem constants: B=8, N=1024, D=768, heads=12, hd=64, H=3072
// ---------------------------------------------------------------------------
#define TOK     8192
#define DIM     768
#define D3      2304
#define NH      12
#define HD      64
#define SEQ     1024
#define HID     3072
#define BH      96

// ---------------- scratch (static device arrays; no cudaMalloc) ------------
__device__ float g_qkv[(size_t)TOK * D3];
__device__ float g_attn[(size_t)TOK * DIM];
__device__ float g_y1[(size_t)TOK * DIM];
__device__ float g_xn[(size_t)TOK * DIM];
__device__ float g_h[(size_t)TOK * HID];
__device__ float g_y2[(size_t)TOK * DIM];
// bf16 split+transposed weights (max N*K over all GEMMs = 3072*768)
__device__ __nv_bfloat16 g_whi[(size_t)3072 * 768];
__device__ __nv_bfloat16 g_wlo[(size_t)3072 * 768];

// ---------------------------------------------------------------------------
// Helpers (base sm_103-safe: mma.sync + ldmatrix + f32x2; NO tcgen05)
// ---------------------------------------------------------------------------
__device__ __forceinline__ uint32_t smem_u32(const void* p) {
    uint32_t a;
    asm("{ .reg .u64 t; cvta.to.shared.u64 t, %1; cvt.u32.u64 %0, t; }" : "=r"(a) : "l"(p));
    return a;
}

__device__ __forceinline__ void ldsm_x4(uint32_t& r0, uint32_t& r1,
                                        uint32_t& r2, uint32_t& r3, uint32_t addr) {
    asm volatile("ldmatrix.sync.aligned.m8n8.x4.shared.b16 {%0,%1,%2,%3}, [%4];"
        : "=r"(r0), "=r"(r1), "=r"(r2), "=r"(r3) : "r"(addr));
}

__device__ __forceinline__ void mma16816(float* c, const uint32_t* a,
                                         uint32_t b0, uint32_t b1) {
    asm volatile(
        "mma.sync.aligned.m16n8k16.row.col.f32.bf16.bf16.f32 "
        "{%0,%1,%2,%3}, {%4,%5,%6,%7}, {%8,%9}, {%0,%1,%2,%3};"
        : "+f"(c[0]), "+f"(c[1]), "+f"(c[2]), "+f"(c[3])
        : "r"(a[0]), "r"(a[1]), "r"(a[2]), "r"(a[3]), "r"(b0), "r"(b1));
}

__device__ __forceinline__ uint32_t pack2_hi(float x, float y, float& lx, float& ly) {
    __nv_bfloat162 h = __floats2bfloat162_rn(x, y);
    float2 hf = __bfloat1622float2(h);
    lx = x - hf.x; ly = y - hf.y;
    return *reinterpret_cast<uint32_t*>(&h);
}
__device__ __forceinline__ uint32_t pack2(float x, float y) {
    __nv_bfloat162 h = __floats2bfloat162_rn(x, y);
    return *reinterpret_cast<uint32_t*>(&h);
}

// ---- packed fp32x2 (FFMA2; compiles on sm_103 per R12 bench) --------------
__device__ __forceinline__ uint64_t f32x2_pack(float lo, float hi) {
    uint64_t r;
    asm("mov.b64 %0, {%1, %2};" : "=l"(r) : "f"(lo), "f"(hi));
    return r;
}
__device__ __forceinline__ void f32x2_unpack(uint64_t v, float& lo, float& hi) {
    asm("mov.b64 {%0, %1}, %2;" : "=f"(lo), "=f"(hi) : "l"(v));
}
__device__ __forceinline__ uint64_t f32x2_fma(uint64_t a, uint64_t b, uint64_t c) {
    uint64_t d;
    asm("fma.rn.f32x2 %0, %1, %2, %3;" : "=l"(d) : "l"(a), "l"(b), "l"(c));
    return d;
}
__device__ __forceinline__ uint64_t f32x2_mul(uint64_t a, uint64_t b) {
    uint64_t d;
    asm("mul.rn.f32x2 %0, %1, %2;" : "=l"(d) : "l"(a), "l"(b));
    return d;
}

// ---------------------------------------------------------------------------
// Weight pre-pass: W[K][N] fp32 -> Whi/Wlo[N][K] bf16 (transpose + hi/lo split).
// ---------------------------------------------------------------------------
__global__ __launch_bounds__(256)
void convert_w(const float* __restrict__ W, __nv_bfloat16* __restrict__ Whi,
               __nv_bfloat16* __restrict__ Wlo, int K, int Nn)
{
    __shared__ float t[32][33];
    const int kBase = blockIdx.y * 32;
    const int nBase = blockIdx.x * 32;
    const int tx = threadIdx.x;        // 0..31
    const int ty = threadIdx.y;        // 0..7

#pragma unroll
    for (int i = 0; i < 4; i++) {
        int k = kBase + ty + i * 8;
        t[ty + i * 8][tx] = W[(size_t)k * Nn + nBase + tx];
    }
    __syncthreads();
#pragma unroll
    for (int i = 0; i < 4; i++) {
        int n = nBase + ty + i * 8;
        float v = t[tx][ty + i * 8];            // = W[kBase+tx][n]
        __nv_bfloat16 h = __float2bfloat16(v);
        float resid = v - __bfloat162float(h);
        Whi[(size_t)n * K + kBase + tx] = h;
        Wlo[(size_t)n * K + kBase + tx] = __float2bfloat16(resid);
    }
}

// ---------------------------------------------------------------------------
// Tensor-core GEMM via mma.sync m16n8k16 bf16 (hi/lo split, fp32 acc in regs).
// C[M,N] = A[M,K] @ W[K,N] (+bias, opt GELU / residual).
// CTA 128x128, BK=32, 8 warps as 4(M)x2(N): 32x64 per warp.
// A smem [m][k], B smem [n][k], both bf16 hi/lo, row stride PADK=40 (80 B,
// 16B-aligned rows; ldmatrix 8-row reads hit all 32 banks once).
// TN fragments: A ldmatrix.x4 no-trans; B ldmatrix.x4 no-trans (2 n-tiles).
// Register-prefetch pipeline: next chunk's LDGs issued before the MMA phase.
// ---------------------------------------------------------------------------
#define PADK 40

template <bool GELU, bool RES>
__global__ __launch_bounds__(256)
void mma_gemm(const float* __restrict__ A,
              const __nv_bfloat16* __restrict__ Whi,
              const __nv_bfloat16* __restrict__ Wlo,
              const float* __restrict__ bias, const float* __restrict__ res,
              float* __restrict__ C, int M, int Nn, int K)
{
    __shared__ __nv_bfloat16 Ah[128][PADK];
    __shared__ __nv_bfloat16 Al[128][PADK];
    __shared__ __nv_bfloat16 Bh[128][PADK];
    __shared__ __nv_bfloat16 Bl[128][PADK];

    const int tid = threadIdx.x;
    const int wid = tid >> 5;
    const int lane = tid & 31;
    const int wm = wid & 3;           // warp row  (0..3) -> 32 M rows
    const int wn = wid >> 2;          // warp col  (0..1) -> 64 N cols
    const int rowBase = blockIdx.y * 128;
    const int colBase = blockIdx.x * 128;

    // staging coords: A tile 128x32 fp32 -> 1024 float4 (4/thread)
    int aR[4], aKG[4];
#pragma unroll
    for (int p = 0; p < 4; p++) { int e = tid + p * 256; aR[p] = e >> 3; aKG[p] = e & 7; }
    // B tile 128x32 bf16 per buffer -> 512 uint4 (2/thread)
    int bN[2], bU[2];
#pragma unroll
    for (int p = 0; p < 2; p++) { int e = tid + p * 256; bN[p] = e >> 2; bU[p] = e & 3; }

    const int nChunks = K / 32;
    float4 pa[4];
    uint4  pbh[2], pbl[2];

    // prologue: prefetch chunk 0
#pragma unroll
    for (int p = 0; p < 4; p++)
        pa[p] = *(const float4*)&A[(size_t)(rowBase + aR[p]) * K + aKG[p] * 4];
#pragma unroll
    for (int p = 0; p < 2; p++) {
        size_t gi = (size_t)(colBase + bN[p]) * K + bU[p] * 8;
        pbh[p] = *(const uint4*)&Whi[gi];
        pbl[p] = *(const uint4*)&Wlo[gi];
    }

    float acc[2][8][4];
#pragma unroll
    for (int mt = 0; mt < 2; mt++)
#pragma unroll
        for (int nt = 0; nt < 8; nt++)
#pragma unroll
            for (int q = 0; q < 4; q++) acc[mt][nt][q] = 0.f;

    // fragment addresses (fixed per thread; ks offset added in-loop)
    //  A: row = wm*32 + mt*16 + (lane&15), col = (lane>>4)*8
    //  B: row = wn*64 + ntp*16 + ((lane>>4)&1)*8 + (lane&7), col = ((lane>>3)&1)*8
    const int aFr = (lane & 15), aFc = (lane >> 4) * 8;
    const int bFr = ((lane >> 4) & 1) * 8 + (lane & 7), bFc = ((lane >> 3) & 1) * 8;

    for (int ch = 0; ch < nChunks; ch++) {
        // --- stage from regs ---
#pragma unroll
        for (int p = 0; p < 4; p++) {
            float lx, ly, lz, lw;
            uint32_t h01 = pack2_hi(pa[p].x, pa[p].y, lx, ly);
            uint32_t h23 = pack2_hi(pa[p].z, pa[p].w, lz, lw);
            *(uint2*)&Ah[aR[p]][aKG[p] * 4] = make_uint2(h01, h23);
            *(uint2*)&Al[aR[p]][aKG[p] * 4] = make_uint2(pack2(lx, ly), pack2(lz, lw));
        }
#pragma unroll
        for (int p = 0; p < 2; p++) {
            *(uint4*)&Bh[bN[p]][bU[p] * 8] = pbh[p];
            *(uint4*)&Bl[bN[p]][bU[p] * 8] = pbl[p];
        }
        __syncthreads();

        // prefetch next chunk (LDG only; consumed next iteration)
        if (ch + 1 < nChunks) {
            const int k0n = (ch + 1) * 32;
#pragma unroll
            for (int p = 0; p < 4; p++)
                pa[p] = *(const float4*)&A[(size_t)(rowBase + aR[p]) * K + k0n + aKG[p] * 4];
#pragma unroll
            for (int p = 0; p < 2; p++) {
                size_t gi = (size_t)(colBase + bN[p]) * K + k0n + bU[p] * 8;
                pbh[p] = *(const uint4*)&Whi[gi];
                pbl[p] = *(const uint4*)&Wlo[gi];
            }
        }

        // --- MMA phase: 2 k-steps of 16 ---
#pragma unroll
        for (int ks = 0; ks < 32; ks += 16) {
            uint32_t ah[2][4], al[2][4];
#pragma unroll
            for (int mt = 0; mt < 2; mt++) {
                uint32_t addrH = smem_u32(&Ah[wm * 32 + mt * 16 + aFr][ks + aFc]);
                ldsm_x4(ah[mt][0], ah[mt][1], ah[mt][2], ah[mt][3], addrH);
                uint32_t addrL = smem_u32(&Al[wm * 32 + mt * 16 + aFr][ks + aFc]);
                ldsm_x4(al[mt][0], al[mt][1], al[mt][2], al[mt][3], addrL);
            }
            uint32_t bh[8][2], bl[8][2];
#pragma unroll
            for (int ntp = 0; ntp < 4; ntp++) {
                uint32_t addrH = smem_u32(&Bh[wn * 64 + ntp * 16 + bFr][ks + bFc]);
                ldsm_x4(bh[ntp*2][0], bh[ntp*2][1], bh[ntp*2+1][0], bh[ntp*2+1][1], addrH);
                uint32_t addrL = smem_u32(&Bl[wn * 64 + ntp * 16 + bFr][ks + bFc]);
                ldsm_x4(bl[ntp*2][0], bl[ntp*2][1], bl[ntp*2+1][0], bl[ntp*2+1][1], addrL);
            }
#pragma unroll
            for (int mt = 0; mt < 2; mt++)
#pragma unroll
                for (int nt = 0; nt < 8; nt++) {
                    mma16816(acc[mt][nt], ah[mt], bh[nt][0], bh[nt][1]);  // hi*hi
                    mma16816(acc[mt][nt], ah[mt], bl[nt][0], bl[nt][1]);  // hi*lo
                    mma16816(acc[mt][nt], al[mt], bh[nt][0], bh[nt][1]);  // lo*hi
                }
        }
        __syncthreads();   // all warps done reading before restaging
    }

    // --- epilogue straight from register fragments ---
    // c frag: c0,c1 -> row (lane>>2), cols 2(lane&3),+1 ; c2,c3 -> row+8
#pragma unroll
    for (int mt = 0; mt < 2; mt++) {
        const int row0 = rowBase + wm * 32 + mt * 16 + (lane >> 2);
#pragma unroll
        for (int nt = 0; nt < 8; nt++) {
            const int col = colBase + wn * 64 + nt * 8 + (lane & 3) * 2;
            float b0 = bias[col], b1 = bias[col + 1];
            float v00 = acc[mt][nt][0] + b0, v01 = acc[mt][nt][1] + b1;
            float v10 = acc[mt][nt][2] + b0, v11 = acc[mt][nt][3] + b1;
            if (GELU) {
                v00 = 0.5f * v00 * (1.f + erff(v00 * 0.70710678118654752f));
                v01 = 0.5f * v01 * (1.f + erff(v01 * 0.70710678118654752f));
                v10 = 0.5f * v10 * (1.f + erff(v10 * 0.70710678118654752f));
                v11 = 0.5f * v11 * (1.f + erff(v11 * 0.70710678118654752f));
            }
            if (RES) {
                float2 r0 = *(const float2*)&res[(size_t)row0 * Nn + col];
                float2 r1 = *(const float2*)&res[(size_t)(row0 + 8) * Nn + col];
                v00 += r0.x; v01 += r0.y; v10 += r1.x; v11 += r1.y;
            }
            *(float2*)&C[(size_t)row0 * Nn + col]       = make_float2(v00, v01);
            *(float2*)&C[(size_t)(row0 + 8) * Nn + col] = make_float2(v10, v11);
        }
    }
}

// ---------------------------------------------------------------------------
// Fused attention (flash-style, exact online softmax), fp32 with packed
// fma.rn.f32x2 inner loops. grid = (SEQ/64, BH), 256 threads.
// DYNAMIC smem: 4 x 64x68 fp32 = 69,632 B (opt-in).
// ---------------------------------------------------------------------------
#define ATTN_TILE  (64 * 68)
#define ATTN_SMEM  (4 * ATTN_TILE * 4)

__global__ __launch_bounds__(256)
void fused_attn_kernel(float* __restrict__ attn)
{
    extern __shared__ float attn_smem[];
    float* Qs = attn_smem;                    // [64][68]
    float* Ks = attn_smem + ATTN_TILE;        // [64][68]
    float* Vs = attn_smem + 2 * ATTN_TILE;    // [64][68]
    float* Ps = attn_smem + 3 * ATTN_TILE;    // [64][68]

    const int tid = threadIdx.x;
    const int tx = tid & 15;
    const int ty = tid >> 4;
    const int bh = blockIdx.y;
    const int b = bh / NH, h = bh % NH;
    const int qBase = blockIdx.x * 64;

    const float* qptr = g_qkv + (size_t)b * SEQ * D3 + h * HD;
    const float* kptr = qptr + DIM;
    const float* vptr = qptr + 2 * DIM;

#pragma unroll
    for (int p = 0; p < 4; p++) {
        int idx = tid + p * 256;
        int r = idx >> 4;
        int c = (idx & 15) * 4;
        float4 qv = *(const float4*)&qptr[(size_t)(qBase + r) * D3 + c];
        Qs[r * 68 + c + 0] = qv.x * 0.125f; Qs[r * 68 + c + 1] = qv.y * 0.125f;
        Qs[r * 68 + c + 2] = qv.z * 0.125f; Qs[r * 68 + c + 3] = qv.w * 0.125f;
    }

    float m[4], l[4];
    uint64_t o2[4][2];
#pragma unroll
    for (int i = 0; i < 4; i++) {
        m[i] = -INFINITY; l[i] = 0.f;
        o2[i][0] = 0ull; o2[i][1] = 0ull;
    }

    for (int kt = 0; kt < SEQ / 64; kt++) {
        const int kBase = kt * 64;
#pragma unroll
        for (int p = 0; p < 4; p++) {
            int idx = tid + p * 256;
            int r = idx >> 4;
            int c = (idx & 15) * 4;
            float4 kv = *(const float4*)&kptr[(size_t)(kBase + r) * D3 + c];
            float4 vv = *(const float4*)&vptr[(size_t)(kBase + r) * D3 + c];
            Ks[r * 68 + c + 0] = kv.x; Ks[r * 68 + c + 1] = kv.y;
            Ks[r * 68 + c + 2] = kv.z; Ks[r * 68 + c + 3] = kv.w;
            Vs[r * 68 + c + 0] = vv.x; Vs[r * 68 + c + 1] = vv.y;
            Vs[r * 68 + c + 2] = vv.z; Vs[r * 68 + c + 3] = vv.w;
        }
        __syncthreads();

        // S = Q K^T : packed pairs along kk (FFMA2)
        uint64_t acc2[4][4];
#pragma unroll
        for (int i = 0; i < 4; i++)
#pragma unroll
            for (int j = 0; j < 4; j++) acc2[i][j] = 0ull;
#pragma unroll
        for (int kk = 0; kk < 64; kk += 4) {
            ulonglong2 q2[4], k2[4];
#pragma unroll
            for (int i = 0; i < 4; i++)
                q2[i] = *(const ulonglong2*)&Qs[(ty * 4 + i) * 68 + kk];
#pragma unroll
            for (int j = 0; j < 4; j++)
                k2[j] = *(const ulonglong2*)&Ks[(tx * 4 + j) * 68 + kk];
#pragma unroll
            for (int i = 0; i < 4; i++)
#pragma unroll
                for (int j = 0; j < 4; j++) {
                    acc2[i][j] = f32x2_fma(q2[i].x, k2[j].x, acc2[i][j]);
                    acc2[i][j] = f32x2_fma(q2[i].y, k2[j].y, acc2[i][j]);
                }
        }
        float s[4][4];
#pragma unroll
        for (int i = 0; i < 4; i++)
#pragma unroll
            for (int j = 0; j < 4; j++) {
                float lo, hi;
                f32x2_unpack(acc2[i][j], lo, hi);
                s[i][j] = lo + hi;
            }

#pragma unroll
        for (int i = 0; i < 4; i++) {
            float tm = fmaxf(fmaxf(s[i][0], s[i][1]), fmaxf(s[i][2], s[i][3]));
#pragma unroll
            for (int off = 8; off > 0; off >>= 1)
                tm = fmaxf(tm, __shfl_xor_sync(0xffffffffu, tm, off, 16));
            float mn = fmaxf(m[i], tm);
            float fac = __expf(m[i] - mn);      // exp(-inf)=0 on first tile
            float p0 = __expf(s[i][0] - mn);
            float p1 = __expf(s[i][1] - mn);
            float p2 = __expf(s[i][2] - mn);
            float p3 = __expf(s[i][3] - mn);
            float rs = p0 + p1 + p2 + p3;
#pragma unroll
            for (int off = 8; off > 0; off >>= 1)
                rs += __shfl_xor_sync(0xffffffffu, rs, off, 16);
            l[i] = l[i] * fac + rs;
            m[i] = mn;
            uint64_t fac2 = f32x2_pack(fac, fac);
            o2[i][0] = f32x2_mul(o2[i][0], fac2);
            o2[i][1] = f32x2_mul(o2[i][1], fac2);
            *(float4*)&Ps[(ty * 4 + i) * 68 + tx * 4] = make_float4(p0, p1, p2, p3);
        }
        __syncthreads();

        // O += P V (FFMA2; P broadcast packs on ALU pipe)
#pragma unroll
        for (int kk = 0; kk < 64; kk += 4) {
            float4 p4[4];
#pragma unroll
            for (int i = 0; i < 4; i++)
                p4[i] = *(const float4*)&Ps[(ty * 4 + i) * 68 + kk];
            ulonglong2 v20 = *(const ulonglong2*)&Vs[(kk + 0) * 68 + tx * 4];
            ulonglong2 v21 = *(const ulonglong2*)&Vs[(kk + 1) * 68 + tx * 4];
            ulonglong2 v22 = *(const ulonglong2*)&Vs[(kk + 2) * 68 + tx * 4];
            ulonglong2 v23 = *(const ulonglong2*)&Vs[(kk + 3) * 68 + tx * 4];
#pragma unroll
            for (int i = 0; i < 4; i++) {
                uint64_t b0 = f32x2_pack(p4[i].x, p4[i].x);
                o2[i][0] = f32x2_fma(b0, v20.x, o2[i][0]);
                o2[i][1] = f32x2_fma(b0, v20.y, o2[i][1]);
                uint64_t b1 = f32x2_pack(p4[i].y, p4[i].y);
                o2[i][0] = f32x2_fma(b1, v21.x, o2[i][0]);
                o2[i][1] = f32x2_fma(b1, v21.y, o2[i][1]);
                uint64_t b2 = f32x2_pack(p4[i].z, p4[i].z);
                o2[i][0] = f32x2_fma(b2, v22.x, o2[i][0]);
                o2[i][1] = f32x2_fma(b2, v22.y, o2[i][1]);
                uint64_t b3 = f32x2_pack(p4[i].w, p4[i].w);
                o2[i][0] = f32x2_fma(b3, v23.x, o2[i][0]);
                o2[i][1] = f32x2_fma(b3, v23.y, o2[i][1]);
            }
        }
        __syncthreads();
    }

#pragma unroll
    for (int i = 0; i < 4; i++) {
        float inv = 1.f / l[i];
        float a0, a1, a2, a3;
        f32x2_unpack(o2[i][0], a0, a1);
        f32x2_unpack(o2[i][1], a2, a3);
        int token = b * SEQ + qBase + ty * 4 + i;
        *(float4*)&attn[(size_t)token * DIM + h * HD + tx * 4] =
            make_float4(a0 * inv, a1 * inv, a2 * inv, a3 * inv);
    }
}

// ---------------------------------------------------------------------------
// LayerNorm over D=768. One block (256 thr, 3 elems each) per row.
// ---------------------------------------------------------------------------
__global__ __launch_bounds__(256)
void layernorm_kernel(const float* __restrict__ in, const float* __restrict__ g,
                      const float* __restrict__ bta, float* __restrict__ out)
{
    __shared__ float sh[16];
    const int tid = threadIdx.x;
    const float* xr = in + (size_t)blockIdx.x * DIM;

    float v0 = xr[tid], v1 = xr[tid + 256], v2 = xr[tid + 512];
    float s = v0 + v1 + v2;
    float q = v0 * v0 + v1 * v1 + v2 * v2;
#pragma unroll
    for (int o = 16; o > 0; o >>= 1) {
        s += __shfl_xor_sync(0xffffffffu, s, o);
        q += __shfl_xor_sync(0xffffffffu, q, o);
    }
    if ((tid & 31) == 0) { sh[tid >> 5] = s; sh[8 + (tid >> 5)] = q; }
    __syncthreads();
    if (tid == 0) {
        float S = 0.f, Q = 0.f;
#pragma unroll
        for (int i = 0; i < 8; i++) { S += sh[i]; Q += sh[8 + i]; }
        sh[0] = S; sh[8] = Q;
    }
    __syncthreads();
    float mean = sh[0] * (1.f / DIM);
    float var = sh[8] * (1.f / DIM) - mean * mean;
    float rstd = rsqrtf(var + 1e-6f);

    float* orow = out + (size_t)blockIdx.x * DIM;
    orow[tid]       = (v0 - mean) * rstd * g[tid]       + bta[tid];
    orow[tid + 256] = (v1 - mean) * rstd * g[tid + 256] + bta[tid + 256];
    orow[tid + 512] = (v2 - mean) * rstd * g[tid + 512] + bta[tid + 512];
}

// ---------------------------------------------------------------------------
// Launch sequence
// ---------------------------------------------------------------------------
extern "C" void kernel_launch(void* const* d_in, const int* in_sizes, int n_in,
                              void* d_out, int out_size)
{
    const float* x      = (const float*)d_in[0];
    const float* qkv_w  = (const float*)d_in[1];
    const float* qkv_b  = (const float*)d_in[2];
    const float* proj_w = (const float*)d_in[3];
    const float* proj_b = (const float*)d_in[4];
    const float* ln1_g  = (const float*)d_in[5];
    const float* ln1_b  = (const float*)d_in[6];
    const float* ln2_g  = (const float*)d_in[7];
    const float* ln2_b  = (const float*)d_in[8];
    const float* fc1_w  = (const float*)d_in[9];
    const float* fc1_b  = (const float*)d_in[10];
    const float* fc2_w  = (const float*)d_in[11];
    const float* fc2_b  = (const float*)d_in[12];
    float* out = (float*)d_out;

    float *qkvbuf, *attn, *y1, *xn, *hbuf, *y2;
    __nv_bfloat16 *whi, *wlo;
    cudaGetSymbolAddress((void**)&qkvbuf, g_qkv);
    cudaGetSymbolAddress((void**)&attn,   g_attn);
    cudaGetSymbolAddress((void**)&y1,     g_y1);
    cudaGetSymbolAddress((void**)&xn,     g_xn);
    cudaGetSymbolAddress((void**)&hbuf,   g_h);
    cudaGetSymbolAddress((void**)&y2,     g_y2);
    cudaGetSymbolAddress((void**)&whi,    g_whi);
    cudaGetSymbolAddress((void**)&wlo,    g_wlo);

    cudaFuncSetAttribute(fused_attn_kernel,
                         cudaFuncAttributeMaxDynamicSharedMemorySize, ATTN_SMEM);

    // 1) QKV = x @ qkv_w + b
    convert_w<<<dim3(D3 / 32, DIM / 32), dim3(32, 8)>>>(qkv_w, whi, wlo, DIM, D3);
    mma_gemm<false, false><<<dim3(D3 / 128, TOK / 128), 256>>>(
        x, whi, wlo, qkv_b, nullptr, qkvbuf, TOK, D3, DIM);

    // 2) fused attention
    fused_attn_kernel<<<dim3(SEQ / 64, BH), 256, ATTN_SMEM>>>(attn);

    // 3) y1 = x + attn @ proj_w + proj_b ; xn = LN1(y1)
    convert_w<<<dim3(DIM / 32, DIM / 32), dim3(32, 8)>>>(proj_w, whi, wlo, DIM, DIM);
    mma_gemm<false, true><<<dim3(DIM / 128, TOK / 128), 256>>>(
        attn, whi, wlo, proj_b, x, y1, TOK, DIM, DIM);
    layernorm_kernel<<<TOK, 256>>>(y1, ln1_g, ln1_b, xn);

    // 4) h = gelu(xn @ fc1_w + fc1_b)
    convert_w<<<dim3(HID / 32, DIM / 32), dim3(32, 8)>>>(fc1_w, whi, wlo, DIM, HID);
    mma_gemm<true, false><<<dim3(HID / 128, TOK / 128), 256>>>(
        xn, whi, wlo, fc1_b, nullptr, hbuf, TOK, HID, DIM);

    // 5) y2 = xn + h @ fc2_w + fc2_b ; out = LN2(y2)
    convert_w<<<dim3(DIM / 32, HID / 32), dim3(32, 8)>>>(fc2_w, whi, wlo, HID, DIM);
    mma_gemm<false, true><<<dim3(DIM / 128, TOK / 128), 256>>>(
        hbuf, whi, wlo, fc2_b, xn, y2, TOK, DIM, HID);
    layernorm_kernel<<<TOK, 256>>>(y2, ln2_g, ln2_b, out);
}

// round 15
// speedup vs baseline: 1.5149x; 1.5149x over previous
#include <cuda_runtime.h>
#include <cuda_bf16.h>
#include <math.h>
#include <stdint.h>

// ---------------------------------------------------------------------------
// Problem constants: B=8, N=1024, D=768, heads=12, hd=64, H=3072
// ---------------------------------------------------------------------------
#define TOK     8192
#define DIM     768
#define D3      2304
#define NH      12
#define HD      64
#define SEQ     1024
#define HID     3072
#define BH      96

// ---------------- scratch (static device arrays; no cudaMalloc) ------------
__device__ float g_qkv[(size_t)TOK * D3];
__device__ float g_attn[(size_t)TOK * DIM];
__device__ float g_y1[(size_t)TOK * DIM];
__device__ float g_xn[(size_t)TOK * DIM];
__device__ float g_h[(size_t)TOK * HID];
__device__ float g_y2[(size_t)TOK * DIM];
// bf16 split+transposed weights (max N*K over all GEMMs = 3072*768)
__device__ __nv_bfloat16 g_whi[(size_t)3072 * 768];
__device__ __nv_bfloat16 g_wlo[(size_t)3072 * 768];

// ---------------------------------------------------------------------------
// Helpers (base sm_103-safe: mma.sync + ldmatrix; validated R13)
// ---------------------------------------------------------------------------
__device__ __forceinline__ uint32_t smem_u32(const void* p) {
    uint32_t a;
    asm("{ .reg .u64 t; cvta.to.shared.u64 t, %1; cvt.u32.u64 %0, t; }" : "=r"(a) : "l"(p));
    return a;
}

__device__ __forceinline__ void ldsm_x4(uint32_t& r0, uint32_t& r1,
                                        uint32_t& r2, uint32_t& r3, uint32_t addr) {
    asm volatile("ldmatrix.sync.aligned.m8n8.x4.shared.b16 {%0,%1,%2,%3}, [%4];"
        : "=r"(r0), "=r"(r1), "=r"(r2), "=r"(r3) : "r"(addr));
}

__device__ __forceinline__ void mma16816(float* c, const uint32_t* a,
                                         uint32_t b0, uint32_t b1) {
    asm volatile(
        "mma.sync.aligned.m16n8k16.row.col.f32.bf16.bf16.f32 "
        "{%0,%1,%2,%3}, {%4,%5,%6,%7}, {%8,%9}, {%0,%1,%2,%3};"
        : "+f"(c[0]), "+f"(c[1]), "+f"(c[2]), "+f"(c[3])
        : "r"(a[0]), "r"(a[1]), "r"(a[2]), "r"(a[3]), "r"(b0), "r"(b1));
}

__device__ __forceinline__ uint32_t pack2_hi(float x, float y, float& lx, float& ly) {
    __nv_bfloat162 h = __floats2bfloat162_rn(x, y);
    float2 hf = __bfloat1622float2(h);
    lx = x - hf.x; ly = y - hf.y;
    return *reinterpret_cast<uint32_t*>(&h);
}
__device__ __forceinline__ uint32_t pack2(float x, float y) {
    __nv_bfloat162 h = __floats2bfloat162_rn(x, y);
    return *reinterpret_cast<uint32_t*>(&h);
}

// ---------------------------------------------------------------------------
// Weight pre-pass: W[K][N] fp32 -> Whi/Wlo[N][K] bf16 (transpose + hi/lo split).
// ---------------------------------------------------------------------------
__global__ __launch_bounds__(256)
void convert_w(const float* __restrict__ W, __nv_bfloat16* __restrict__ Whi,
               __nv_bfloat16* __restrict__ Wlo, int K, int Nn)
{
    __shared__ float t[32][33];
    const int kBase = blockIdx.y * 32;
    const int nBase = blockIdx.x * 32;
    const int tx = threadIdx.x;        // 0..31
    const int ty = threadIdx.y;        // 0..7

#pragma unroll
    for (int i = 0; i < 4; i++) {
        int k = kBase + ty + i * 8;
        t[ty + i * 8][tx] = W[(size_t)k * Nn + nBase + tx];
    }
    __syncthreads();
#pragma unroll
    for (int i = 0; i < 4; i++) {
        int n = nBase + ty + i * 8;
        float v = t[tx][ty + i * 8];            // = W[kBase+tx][n]
        __nv_bfloat16 h = __float2bfloat16(v);
        float resid = v - __bfloat162float(h);
        Whi[(size_t)n * K + kBase + tx] = h;
        Wlo[(size_t)n * K + kBase + tx] = __float2bfloat16(resid);
    }
}

// ---------------------------------------------------------------------------
// Tensor-core GEMM via mma.sync m16n8k16 bf16 (hi/lo split, fp32 acc in regs).
// Fragment/epilogue logic BYTE-IDENTICAL to the bench-validated R13 kernel
// (rel_err 7.1e-6). NEW: double-buffered dynamic smem — one __syncthreads per
// BK=32 chunk; next chunk's LDGs overlap the MMA phase.
// Hazard proof: stage into buf[(ch+1)&1] in iter ch occurs after the barrier
// at the top of iter ch, which all warps pass only after finishing iter ch-1's
// MMA — the last reader of that buffer.
// Dyn smem: 2 buffers x (Ah|Al|Bh|Bl)[128][PADK] bf16 = 81,920 B.
// ---------------------------------------------------------------------------
#define PADK 40
#define GEMM_BUF (4 * 128 * PADK)                 // bf16 elems per buffer set
#define GEMM_SMEM (2 * GEMM_BUF * 2)              // bytes

template <bool GELU, bool RES>
__global__ __launch_bounds__(256)
void mma_gemm(const float* __restrict__ A,
              const __nv_bfloat16* __restrict__ Whi,
              const __nv_bfloat16* __restrict__ Wlo,
              const float* __restrict__ bias, const float* __restrict__ res,
              float* __restrict__ C, int M, int Nn, int K)
{
    extern __shared__ __nv_bfloat16 gsm[];

    const int tid = threadIdx.x;
    const int wid = tid >> 5;
    const int lane = tid & 31;
    const int wm = wid & 3;
    const int wn = wid >> 2;
    const int rowBase = blockIdx.y * 128;
    const int colBase = blockIdx.x * 128;

    int aR[4], aKG[4];
#pragma unroll
    for (int p = 0; p < 4; p++) { int e = tid + p * 256; aR[p] = e >> 3; aKG[p] = e & 7; }
    int bN[2], bU[2];
#pragma unroll
    for (int p = 0; p < 2; p++) { int e = tid + p * 256; bN[p] = e >> 2; bU[p] = e & 3; }

    const int nChunks = K / 32;
    float4 pa[4];
    uint4  pbh[2], pbl[2];

    // prologue: prefetch chunk 0 and stage it into buffer 0
#pragma unroll
    for (int p = 0; p < 4; p++)
        pa[p] = *(const float4*)&A[(size_t)(rowBase + aR[p]) * K + aKG[p] * 4];
#pragma unroll
    for (int p = 0; p < 2; p++) {
        size_t gi = (size_t)(colBase + bN[p]) * K + bU[p] * 8;
        pbh[p] = *(const uint4*)&Whi[gi];
        pbl[p] = *(const uint4*)&Wlo[gi];
    }
    {
        __nv_bfloat16* Ah = gsm;
        __nv_bfloat16* Al = gsm + 128 * PADK;
        __nv_bfloat16* Bh = gsm + 2 * 128 * PADK;
        __nv_bfloat16* Bl = gsm + 3 * 128 * PADK;
#pragma unroll
        for (int p = 0; p < 4; p++) {
            float lx, ly, lz, lw;
            uint32_t h01 = pack2_hi(pa[p].x, pa[p].y, lx, ly);
            uint32_t h23 = pack2_hi(pa[p].z, pa[p].w, lz, lw);
            *(uint2*)&Ah[aR[p] * PADK + aKG[p] * 4] = make_uint2(h01, h23);
            *(uint2*)&Al[aR[p] * PADK + aKG[p] * 4] = make_uint2(pack2(lx, ly), pack2(lz, lw));
        }
#pragma unroll
        for (int p = 0; p < 2; p++) {
            *(uint4*)&Bh[bN[p] * PADK + bU[p] * 8] = pbh[p];
            *(uint4*)&Bl[bN[p] * PADK + bU[p] * 8] = pbl[p];
        }
    }

    float acc[2][8][4];
#pragma unroll
    for (int mt = 0; mt < 2; mt++)
#pragma unroll
        for (int nt = 0; nt < 8; nt++)
#pragma unroll
            for (int q = 0; q < 4; q++) acc[mt][nt][q] = 0.f;

    const int aFr = (lane & 15), aFc = (lane >> 4) * 8;
    const int bFr = ((lane >> 4) & 1) * 8 + (lane & 7), bFc = ((lane >> 3) & 1) * 8;

    for (int ch = 0; ch < nChunks; ch++) {
        __syncthreads();   // buf[ch&1] staged & safe; also releases buf[(ch+1)&1]

        // prefetch chunk ch+1 (LDG only; overlaps the MMA phase below)
        if (ch + 1 < nChunks) {
            const int k0n = (ch + 1) * 32;
#pragma unroll
            for (int p = 0; p < 4; p++)
                pa[p] = *(const float4*)&A[(size_t)(rowBase + aR[p]) * K + k0n + aKG[p] * 4];
#pragma unroll
            for (int p = 0; p < 2; p++) {
                size_t gi = (size_t)(colBase + bN[p]) * K + k0n + bU[p] * 8;
                pbh[p] = *(const uint4*)&Whi[gi];
                pbl[p] = *(const uint4*)&Wlo[gi];
            }
        }

        const __nv_bfloat16* Ah = gsm + (size_t)(ch & 1) * GEMM_BUF;
        const __nv_bfloat16* Al = Ah + 128 * PADK;
        const __nv_bfloat16* Bh = Ah + 2 * 128 * PADK;
        const __nv_bfloat16* Bl = Ah + 3 * 128 * PADK;

#pragma unroll
        for (int ks = 0; ks < 32; ks += 16) {
            uint32_t ah[2][4], al[2][4];
#pragma unroll
            for (int mt = 0; mt < 2; mt++) {
                ldsm_x4(ah[mt][0], ah[mt][1], ah[mt][2], ah[mt][3],
                        smem_u32(&Ah[(wm * 32 + mt * 16 + aFr) * PADK + ks + aFc]));
                ldsm_x4(al[mt][0], al[mt][1], al[mt][2], al[mt][3],
                        smem_u32(&Al[(wm * 32 + mt * 16 + aFr) * PADK + ks + aFc]));
            }
            uint32_t bh[8][2], bl[8][2];
#pragma unroll
            for (int ntp = 0; ntp < 4; ntp++) {
                ldsm_x4(bh[ntp*2][0], bh[ntp*2][1], bh[ntp*2+1][0], bh[ntp*2+1][1],
                        smem_u32(&Bh[(wn * 64 + ntp * 16 + bFr) * PADK + ks + bFc]));
                ldsm_x4(bl[ntp*2][0], bl[ntp*2][1], bl[ntp*2+1][0], bl[ntp*2+1][1],
                        smem_u32(&Bl[(wn * 64 + ntp * 16 + bFr) * PADK + ks + bFc]));
            }
#pragma unroll
            for (int mt = 0; mt < 2; mt++)
#pragma unroll
                for (int nt = 0; nt < 8; nt++) {
                    mma16816(acc[mt][nt], ah[mt], bh[nt][0], bh[nt][1]);
                    mma16816(acc[mt][nt], ah[mt], bl[nt][0], bl[nt][1]);
                    mma16816(acc[mt][nt], al[mt], bh[nt][0], bh[nt][1]);
                }
        }

        // stage chunk ch+1 into the other buffer (safe per hazard proof above)
        if (ch + 1 < nChunks) {
            __nv_bfloat16* nAh = gsm + (size_t)((ch + 1) & 1) * GEMM_BUF;
            __nv_bfloat16* nAl = nAh + 128 * PADK;
            __nv_bfloat16* nBh = nAh + 2 * 128 * PADK;
            __nv_bfloat16* nBl = nAh + 3 * 128 * PADK;
#pragma unroll
            for (int p = 0; p < 4; p++) {
                float lx, ly, lz, lw;
                uint32_t h01 = pack2_hi(pa[p].x, pa[p].y, lx, ly);
                uint32_t h23 = pack2_hi(pa[p].z, pa[p].w, lz, lw);
                *(uint2*)&nAh[aR[p] * PADK + aKG[p] * 4] = make_uint2(h01, h23);
                *(uint2*)&nAl[aR[p] * PADK + aKG[p] * 4] = make_uint2(pack2(lx, ly), pack2(lz, lw));
            }
#pragma unroll
            for (int p = 0; p < 2; p++) {
                *(uint4*)&nBh[bN[p] * PADK + bU[p] * 8] = pbh[p];
                *(uint4*)&nBl[bN[p] * PADK + bU[p] * 8] = pbl[p];
            }
        }
    }

    // --- epilogue (unchanged, validated) ---
#pragma unroll
    for (int mt = 0; mt < 2; mt++) {
        const int row0 = rowBase + wm * 32 + mt * 16 + (lane >> 2);
#pragma unroll
        for (int nt = 0; nt < 8; nt++) {
            const int col = colBase + wn * 64 + nt * 8 + (lane & 3) * 2;
            float b0 = bias[col], b1 = bias[col + 1];
            float v00 = acc[mt][nt][0] + b0, v01 = acc[mt][nt][1] + b1;
            float v10 = acc[mt][nt][2] + b0, v11 = acc[mt][nt][3] + b1;
            if (GELU) {
                v00 = 0.5f * v00 * (1.f + erff(v00 * 0.70710678118654752f));
                v01 = 0.5f * v01 * (1.f + erff(v01 * 0.70710678118654752f));
                v10 = 0.5f * v10 * (1.f + erff(v10 * 0.70710678118654752f));
                v11 = 0.5f * v11 * (1.f + erff(v11 * 0.70710678118654752f));
            }
            if (RES) {
                float2 r0 = *(const float2*)&res[(size_t)row0 * Nn + col];
                float2 r1 = *(const float2*)&res[(size_t)(row0 + 8) * Nn + col];
                v00 += r0.x; v01 += r0.y; v10 += r1.x; v11 += r1.y;
            }
            *(float2*)&C[(size_t)row0 * Nn + col]       = make_float2(v00, v01);
            *(float2*)&C[(size_t)(row0 + 8) * Nn + col] = make_float2(v10, v11);
        }
    }
}

// ---------------------------------------------------------------------------
// Tensor-core flash attention (mma.sync, hi/lo split, exact online softmax).
// Unchanged from R14 (re-audited: fragment maps consistent with the
// bench-validated GEMM ldmatrix order).
// ---------------------------------------------------------------------------
#define APADK 72
#define ATTN_SMEM ((128 * APADK * 2 + 64 * APADK * 2 + 64 * APADK * 2) * 2)

__global__ __launch_bounds__(256)
void fused_attn_tc(float* __restrict__ attn)
{
    extern __shared__ __nv_bfloat16 asmem[];
    __nv_bfloat16* Qh = asmem;                     // [128][72]
    __nv_bfloat16* Ql = Qh + 128 * APADK;
    __nv_bfloat16* Kh = Ql + 128 * APADK;          // [64][72]
    __nv_bfloat16* Kl = Kh + 64 * APADK;
    __nv_bfloat16* Vh = Kl + 64 * APADK;           // [64][72] = V^T: [d][k]
    __nv_bfloat16* Vl = Vh + 64 * APADK;

    const int tid = threadIdx.x;
    const int wid = tid >> 5;
    const int lane = tid & 31;
    const int g = lane >> 2;
    const int c = lane & 3;
    const int bh = blockIdx.y;
    const int b = bh / NH, h = bh % NH;
    const int qBase = blockIdx.x * 128;

    const float* qptr = g_qkv + (size_t)b * SEQ * D3 + h * HD;
    const float* kptr = qptr + DIM;
    const float* vptr = qptr + 2 * DIM;

#pragma unroll
    for (int p = 0; p < 8; p++) {
        int e = tid + p * 256;
        int r = e >> 4;
        int cg = e & 15;
        float4 qv = *(const float4*)&qptr[(size_t)(qBase + r) * D3 + cg * 4];
        qv.x *= 0.125f; qv.y *= 0.125f; qv.z *= 0.125f; qv.w *= 0.125f;
        float lx, ly, lz, lw;
        uint32_t h01 = pack2_hi(qv.x, qv.y, lx, ly);
        uint32_t h23 = pack2_hi(qv.z, qv.w, lz, lw);
        *(uint2*)&Qh[r * APADK + cg * 4] = make_uint2(h01, h23);
        *(uint2*)&Ql[r * APADK + cg * 4] = make_uint2(pack2(lx, ly), pack2(lz, lw));
    }

    float sM[2] = {-INFINITY, -INFINITY};
    float sL[2] = {0.f, 0.f};
    float o[8][4];
#pragma unroll
    for (int nt = 0; nt < 8; nt++)
#pragma unroll
        for (int q = 0; q < 4; q++) o[nt][q] = 0.f;

    const int aFr = (lane & 15), aFc = (lane >> 4) * 8;
    const int bFr = ((lane >> 4) & 1) * 8 + (lane & 7), bFc = ((lane >> 3) & 1) * 8;
    const int qRow = wid * 16;

    for (int kt = 0; kt < SEQ / 64; kt++) {
        const int kBase = kt * 64;
#pragma unroll
        for (int p = 0; p < 4; p++) {
            int e = tid + p * 256;
            int r = e >> 4;
            int cg = e & 15;
            float4 kv = *(const float4*)&kptr[(size_t)(kBase + r) * D3 + cg * 4];
            float lx, ly, lz, lw;
            uint32_t h01 = pack2_hi(kv.x, kv.y, lx, ly);
            uint32_t h23 = pack2_hi(kv.z, kv.w, lz, lw);
            *(uint2*)&Kh[r * APADK + cg * 4] = make_uint2(h01, h23);
            *(uint2*)&Kl[r * APADK + cg * 4] = make_uint2(pack2(lx, ly), pack2(lz, lw));
        }
#pragma unroll
        for (int p = 0; p < 4; p++) {
            int e = tid + p * 256;
            int k = e >> 4;
            int d4 = (e & 15) * 4;
            float4 vv = *(const float4*)&vptr[(size_t)(kBase + k) * D3 + d4];
            const float* vp = &vv.x;
#pragma unroll
            for (int j = 0; j < 4; j++) {
                float x = vp[j];
                __nv_bfloat16 hi = __float2bfloat16(x);
                Vh[(d4 + j) * APADK + k] = hi;
                Vl[(d4 + j) * APADK + k] = __float2bfloat16(x - __bfloat162float(hi));
            }
        }
        __syncthreads();

        float sf[8][4];
#pragma unroll
        for (int nt = 0; nt < 8; nt++)
#pragma unroll
            for (int q = 0; q < 4; q++) sf[nt][q] = 0.f;
#pragma unroll
        for (int ks = 0; ks < 4; ks++) {
            uint32_t qh4[4], ql4[4];
            ldsm_x4(qh4[0], qh4[1], qh4[2], qh4[3],
                    smem_u32(&Qh[(qRow + aFr) * APADK + ks * 16 + aFc]));
            ldsm_x4(ql4[0], ql4[1], ql4[2], ql4[3],
                    smem_u32(&Ql[(qRow + aFr) * APADK + ks * 16 + aFc]));
            uint32_t kh4[8][2], kl4[8][2];
#pragma unroll
            for (int ntp = 0; ntp < 4; ntp++) {
                ldsm_x4(kh4[ntp*2][0], kh4[ntp*2][1], kh4[ntp*2+1][0], kh4[ntp*2+1][1],
                        smem_u32(&Kh[(ntp * 16 + bFr) * APADK + ks * 16 + bFc]));
                ldsm_x4(kl4[ntp*2][0], kl4[ntp*2][1], kl4[ntp*2+1][0], kl4[ntp*2+1][1],
                        smem_u32(&Kl[(ntp * 16 + bFr) * APADK + ks * 16 + bFc]));
            }
#pragma unroll
            for (int nt = 0; nt < 8; nt++) {
                mma16816(sf[nt], qh4, kh4[nt][0], kh4[nt][1]);
                mma16816(sf[nt], qh4, kl4[nt][0], kl4[nt][1]);
                mma16816(sf[nt], ql4, kh4[nt][0], kh4[nt][1]);
            }
        }

        float tm0 = -INFINITY, tm1 = -INFINITY;
#pragma unroll
        for (int nt = 0; nt < 8; nt++) {
            tm0 = fmaxf(tm0, fmaxf(sf[nt][0], sf[nt][1]));
            tm1 = fmaxf(tm1, fmaxf(sf[nt][2], sf[nt][3]));
        }
#pragma unroll
        for (int off = 1; off <= 2; off <<= 1) {
            tm0 = fmaxf(tm0, __shfl_xor_sync(0xffffffffu, tm0, off));
            tm1 = fmaxf(tm1, __shfl_xor_sync(0xffffffffu, tm1, off));
        }
        float mn0 = fmaxf(sM[0], tm0), mn1 = fmaxf(sM[1], tm1);
        float fac0 = __expf(sM[0] - mn0), fac1 = __expf(sM[1] - mn1);
        sM[0] = mn0; sM[1] = mn1;

        uint32_t ph[4][4], pl[4][4];
        float rs0 = 0.f, rs1 = 0.f;
#pragma unroll
        for (int nt = 0; nt < 8; nt++) {
            float e0 = __expf(sf[nt][0] - mn0);
            float e1 = __expf(sf[nt][1] - mn0);
            float e2 = __expf(sf[nt][2] - mn1);
            float e3 = __expf(sf[nt][3] - mn1);
            rs0 += e0 + e1; rs1 += e2 + e3;
            int ks = nt >> 1, half = nt & 1;
            float l0, l1, l2, l3;
            uint32_t h01 = pack2_hi(e0, e1, l0, l1);
            uint32_t h23 = pack2_hi(e2, e3, l2, l3);
            ph[ks][half * 2 + 0] = h01; ph[ks][half * 2 + 1] = h23;
            pl[ks][half * 2 + 0] = pack2(l0, l1);
            pl[ks][half * 2 + 1] = pack2(l2, l3);
        }
#pragma unroll
        for (int off = 1; off <= 2; off <<= 1) {
            rs0 += __shfl_xor_sync(0xffffffffu, rs0, off);
            rs1 += __shfl_xor_sync(0xffffffffu, rs1, off);
        }
        sL[0] = sL[0] * fac0 + rs0;
        sL[1] = sL[1] * fac1 + rs1;
#pragma unroll
        for (int nt = 0; nt < 8; nt++) {
            o[nt][0] *= fac0; o[nt][1] *= fac0;
            o[nt][2] *= fac1; o[nt][3] *= fac1;
        }

#pragma unroll
        for (int ks = 0; ks < 4; ks++) {
            uint32_t vh4[8][2], vl4[8][2];
#pragma unroll
            for (int dtp = 0; dtp < 4; dtp++) {
                ldsm_x4(vh4[dtp*2][0], vh4[dtp*2][1], vh4[dtp*2+1][0], vh4[dtp*2+1][1],
                        smem_u32(&Vh[(dtp * 16 + bFr) * APADK + ks * 16 + bFc]));
                ldsm_x4(vl4[dtp*2][0], vl4[dtp*2][1], vl4[dtp*2+1][0], vl4[dtp*2+1][1],
                        smem_u32(&Vl[(dtp * 16 + bFr) * APADK + ks * 16 + bFc]));
            }
#pragma unroll
            for (int dt = 0; dt < 8; dt++) {
                mma16816(o[dt], ph[ks], vh4[dt][0], vh4[dt][1]);
                mma16816(o[dt], ph[ks], vl4[dt][0], vl4[dt][1]);
                mma16816(o[dt], pl[ks], vh4[dt][0], vh4[dt][1]);
            }
        }
        __syncthreads();
    }

    float inv0 = 1.f / sL[0], inv1 = 1.f / sL[1];
    const int tok0 = b * SEQ + qBase + qRow + g;
#pragma unroll
    for (int nt = 0; nt < 8; nt++) {
        const int col = h * HD + nt * 8 + c * 2;
        *(float2*)&attn[(size_t)tok0 * DIM + col] =
            make_float2(o[nt][0] * inv0, o[nt][1] * inv0);
        *(float2*)&attn[(size_t)(tok0 + 8) * DIM + col] =
            make_float2(o[nt][2] * inv1, o[nt][3] * inv1);
    }
}

// ---------------------------------------------------------------------------
// LayerNorm over D=768. One block (256 thr, 3 elems each) per row.
// ---------------------------------------------------------------------------
__global__ __launch_bounds__(256)
void layernorm_kernel(const float* __restrict__ in, const float* __restrict__ g,
                      const float* __restrict__ bta, float* __restrict__ out)
{
    __shared__ float sh[16];
    const int tid = threadIdx.x;
    const float* xr = in + (size_t)blockIdx.x * DIM;

    float v0 = xr[tid], v1 = xr[tid + 256], v2 = xr[tid + 512];
    float s = v0 + v1 + v2;
    float q = v0 * v0 + v1 * v1 + v2 * v2;
#pragma unroll
    for (int o = 16; o > 0; o >>= 1) {
        s += __shfl_xor_sync(0xffffffffu, s, o);
        q += __shfl_xor_sync(0xffffffffu, q, o);
    }
    if ((tid & 31) == 0) { sh[tid >> 5] = s; sh[8 + (tid >> 5)] = q; }
    __syncthreads();
    if (tid == 0) {
        float S = 0.f, Q = 0.f;
#pragma unroll
        for (int i = 0; i < 8; i++) { S += sh[i]; Q += sh[8 + i]; }
        sh[0] = S; sh[8] = Q;
    }
    __syncthreads();
    float mean = sh[0] * (1.f / DIM);
    float var = sh[8] * (1.f / DIM) - mean * mean;
    float rstd = rsqrtf(var + 1e-6f);

    float* orow = out + (size_t)blockIdx.x * DIM;
    orow[tid]       = (v0 - mean) * rstd * g[tid]       + bta[tid];
    orow[tid + 256] = (v1 - mean) * rstd * g[tid + 256] + bta[tid + 256];
    orow[tid + 512] = (v2 - mean) * rstd * g[tid + 512] + bta[tid + 512];
}

// ---------------------------------------------------------------------------
// Launch sequence
// ---------------------------------------------------------------------------
extern "C" void kernel_launch(void* const* d_in, const int* in_sizes, int n_in,
                              void* d_out, int out_size)
{
    const float* x      = (const float*)d_in[0];
    const float* qkv_w  = (const float*)d_in[1];
    const float* qkv_b  = (const float*)d_in[2];
    const float* proj_w = (const float*)d_in[3];
    const float* proj_b = (const float*)d_in[4];
    const float* ln1_g  = (const float*)d_in[5];
    const float* ln1_b  = (const float*)d_in[6];
    const float* ln2_g  = (const float*)d_in[7];
    const float* ln2_b  = (const float*)d_in[8];
    const float* fc1_w  = (const float*)d_in[9];
    const float* fc1_b  = (const float*)d_in[10];
    const float* fc2_w  = (const float*)d_in[11];
    const float* fc2_b  = (const float*)d_in[12];
    float* out = (float*)d_out;

    float *qkvbuf, *attn, *y1, *xn, *hbuf, *y2;
    __nv_bfloat16 *whi, *wlo;
    cudaGetSymbolAddress((void**)&qkvbuf, g_qkv);
    cudaGetSymbolAddress((void**)&attn,   g_attn);
    cudaGetSymbolAddress((void**)&y1,     g_y1);
    cudaGetSymbolAddress((void**)&xn,     g_xn);
    cudaGetSymbolAddress((void**)&hbuf,   g_h);
    cudaGetSymbolAddress((void**)&y2,     g_y2);
    cudaGetSymbolAddress((void**)&whi,    g_whi);
    cudaGetSymbolAddress((void**)&wlo,    g_wlo);

    cudaFuncSetAttribute(mma_gemm<false, false>,
                         cudaFuncAttributeMaxDynamicSharedMemorySize, GEMM_SMEM);
    cudaFuncSetAttribute(mma_gemm<false, true>,
                         cudaFuncAttributeMaxDynamicSharedMemorySize, GEMM_SMEM);
    cudaFuncSetAttribute(mma_gemm<true, false>,
                         cudaFuncAttributeMaxDynamicSharedMemorySize, GEMM_SMEM);
    cudaFuncSetAttribute(fused_attn_tc,
                         cudaFuncAttributeMaxDynamicSharedMemorySize, ATTN_SMEM);

    // 1) QKV = x @ qkv_w + b
    convert_w<<<dim3(D3 / 32, DIM / 32), dim3(32, 8)>>>(qkv_w, whi, wlo, DIM, D3);
    mma_gemm<false, false><<<dim3(D3 / 128, TOK / 128), 256, GEMM_SMEM>>>(
        x, whi, wlo, qkv_b, nullptr, qkvbuf, TOK, D3, DIM);

    // 2) fused attention (tensor-core flash)
    fused_attn_tc<<<dim3(SEQ / 128, BH), 256, ATTN_SMEM>>>(attn);

    // 3) y1 = x + attn @ proj_w + proj_b ; xn = LN1(y1)
    convert_w<<<dim3(DIM / 32, DIM / 32), dim3(32, 8)>>>(proj_w, whi, wlo, DIM, DIM);
    mma_gemm<false, true><<<dim3(DIM / 128, TOK / 128), 256, GEMM_SMEM>>>(
        attn, whi, wlo, proj_b, x, y1, TOK, DIM, DIM);
    layernorm_kernel<<<TOK, 256>>>(y1, ln1_g, ln1_b, xn);

    // 4) h = gelu(xn @ fc1_w + fc1_b)
    convert_w<<<dim3(HID / 32, DIM / 32), dim3(32, 8)>>>(fc1_w, whi, wlo, DIM, HID);
    mma_gemm<true, false><<<dim3(HID / 128, TOK / 128), 256, GEMM_SMEM>>>(
        xn, whi, wlo, fc1_b, nullptr, hbuf, TOK, HID, DIM);

    // 5) y2 = xn + h @ fc2_w + fc2_b ; out = LN2(y2)
    convert_w<<<dim3(DIM / 32, HID / 32), dim3(32, 8)>>>(fc2_w, whi, wlo, HID, DIM);
    mma_gemm<false, true><<<dim3(DIM / 128, TOK / 128), 256, GEMM_SMEM>>>(
        hbuf, whi, wlo, fc2_b, xn, y2, TOK, DIM, HID);
    layernorm_kernel<<<TOK, 256>>>(y2, ln2_g, ln2_b, out);
}